// round 15
// baseline (speedup 1.0000x reference)
#include <cuda_runtime.h>
#include <cuda_fp16.h>
#include <cstdint>

// Head-axis-softmax attention, HMMA fp16/f32. R15:
//  - 2 CTAs/SM co-residency: S_TILE=32, 256 threads (8 warps, warp = head),
//    grid 256 (all CTAs resident on 148 SMs)
//  - smem 114688 B/CTA: Q/K/V swizzled (SW128/SW64), EW 64B-row swizzled
//  - V single-buffer phase-shifted, K phase-shifted (R13 flow: 4 bars + 2 waits)
//  - pre-pass converts Q (scale folded), K, V to f16
// B=2,H=8,S=4096,d=64. Warp h covers 32 s-rows (2 m-tiles), B-frags shared.

namespace {
constexpr int NH = 8, SEQ = 4096, D = 64;
constexpr int S_TILE = 32, T_TILE = 32;
constexpr int THREADS = 256;
constexpr float SCALE = 0.044194173824159216f;   // 1/sqrt(512)

constexpr int KS_H = 64 * 64;        // K: per head 64 k-rows x 64B (32 t f16), SW64
constexpr int VS_H = 32 * 128;       // V: per head 32 t-rows x 128B (64 dv f16), SW128
constexpr int QS_H = 32 * 128;       // Q: per head 32 s-rows x 128B (64 k f16), SW128
constexpr int EW_H = 32 * 64;        // E/W: per head 32 s-rows x 64B (32 t f16), swizzled

constexpr int SM_K  = 0;                      // 32768
constexpr int SM_V  = NH * KS_H;              // 32768..65536
constexpr int SM_Q  = SM_V + NH * VS_H;       // 65536..98304
constexpr int SM_EW = SM_Q + NH * QS_H;       // 98304..114688
constexpr int SMEM_BYTES = SM_EW + NH * EW_H; // 114688 (2 CTAs: 229376 <= 232448)

constexpr int KV_ELEMS = 2 * NH * D * SEQ;
}

static __device__ __align__(16) __half g_Q16[KV_ELEMS];   // pre-scaled
static __device__ __align__(16) __half g_K16[KV_ELEMS];
static __device__ __align__(16) __half g_V16[KV_ELEMS];

__global__ __launch_bounds__(256) void cvt_qkv_kernel(const float* __restrict__ Q,
                                                      const float* __restrict__ K,
                                                      const float* __restrict__ V) {
    const int i = (blockIdx.x * 256 + threadIdx.x) * 8;
    {
        float4 a = *(const float4*)(Q + i);
        float4 b = *(const float4*)(Q + i + 4);
        __half2 p[4] = { __floats2half2_rn(a.x * SCALE, a.y * SCALE),
                         __floats2half2_rn(a.z * SCALE, a.w * SCALE),
                         __floats2half2_rn(b.x * SCALE, b.y * SCALE),
                         __floats2half2_rn(b.z * SCALE, b.w * SCALE) };
        *(uint4*)&g_Q16[i] = *(const uint4*)p;
    }
    {
        float4 a = *(const float4*)(K + i);
        float4 b = *(const float4*)(K + i + 4);
        __half2 p[4] = { __floats2half2_rn(a.x, a.y), __floats2half2_rn(a.z, a.w),
                         __floats2half2_rn(b.x, b.y), __floats2half2_rn(b.z, b.w) };
        *(uint4*)&g_K16[i] = *(const uint4*)p;
    }
    {
        float4 a = *(const float4*)(V + i);
        float4 b = *(const float4*)(V + i + 4);
        __half2 p[4] = { __floats2half2_rn(a.x, a.y), __floats2half2_rn(a.z, a.w),
                         __floats2half2_rn(b.x, b.y), __floats2half2_rn(b.z, b.w) };
        *(uint4*)&g_V16[i] = *(const uint4*)p;
    }
}

static __device__ __forceinline__ uint32_t smem_u32(const void* p) {
    uint32_t a;
    asm("{ .reg .u64 t; cvta.to.shared.u64 t, %1; cvt.u32.u64 %0, t; }" : "=r"(a) : "l"(p));
    return a;
}
static __device__ __forceinline__ void cp16(uint32_t dst, const void* src) {
    asm volatile("cp.async.cg.shared.global [%0], [%1], 16;" :: "r"(dst), "l"(src));
}
static __device__ __forceinline__ void cp_commit() {
    asm volatile("cp.async.commit_group;" ::: "memory");
}
static __device__ __forceinline__ void cp_wait0() {
    asm volatile("cp.async.wait_group 0;" ::: "memory");
}
static __device__ __forceinline__ void cp_wait1() {
    asm volatile("cp.async.wait_group 1;" ::: "memory");
}
static __device__ __forceinline__ void ldsm_x4(uint32_t* r, uint32_t a) {
    asm volatile("ldmatrix.sync.aligned.m8n8.x4.shared.b16 {%0,%1,%2,%3}, [%4];"
        : "=r"(r[0]), "=r"(r[1]), "=r"(r[2]), "=r"(r[3]) : "r"(a));
}
static __device__ __forceinline__ void ldsm_x2t(uint32_t* r, uint32_t a) {
    asm volatile("ldmatrix.sync.aligned.m8n8.x2.trans.shared.b16 {%0,%1}, [%2];"
        : "=r"(r[0]), "=r"(r[1]) : "r"(a));
}
static __device__ __forceinline__ void mma16816(float* c, const uint32_t* a, const uint32_t* b) {
    asm volatile("mma.sync.aligned.m16n8k16.row.col.f32.f16.f16.f32 "
        "{%0,%1,%2,%3}, {%4,%5,%6,%7}, {%8,%9}, {%0,%1,%2,%3};"
        : "+f"(c[0]), "+f"(c[1]), "+f"(c[2]), "+f"(c[3])
        : "r"(a[0]), "r"(a[1]), "r"(a[2]), "r"(a[3]), "r"(b[0]), "r"(b[1]));
}
static __device__ __forceinline__ uint32_t packh2(float x, float y) {
    __half2 h = __floats2half2_rn(x, y);
    return *(const uint32_t*)&h;
}

__global__ __launch_bounds__(THREADS, 2)
void attn_hmma_kernel(float* __restrict__ O)
{
    extern __shared__ char smem[];
    const uint32_t sb = smem_u32(smem);
    const int tid  = threadIdx.x;
    const int h    = tid >> 5, lane = tid & 31;   // warp == head
    const int b    = blockIdx.x >> 7;
    const int s0   = (blockIdx.x & 127) * S_TILE;

    const size_t kv16 = (size_t)b * NH * D * SEQ;

    auto prefetch_K = [&](int t0) {
        #pragma unroll
        for (int i = 0; i < 8; ++i) {
            const int f = tid + i * THREADS;          // 0..2047 16B chunks
            const int kh = f >> 8, rem = f & 255;
            const int k = rem >> 2, tc = rem & 3;
            cp16(sb + SM_K + kh * KS_H + k * 64 + ((tc ^ (k & 3)) << 4),
                 g_K16 + kv16 + (size_t)(kh * D + k) * SEQ + t0 + tc * 8);
        }
    };
    auto prefetch_V = [&](int t0) {
        #pragma unroll
        for (int i = 0; i < 8; ++i) {
            const int f = tid + i * THREADS;
            const int vh = f >> 8, rem = f & 255;
            const int t = rem >> 3, dc = rem & 7;
            cp16(sb + SM_V + vh * VS_H + t * 128 + ((dc ^ (t & 7)) << 4),
                 g_V16 + kv16 + ((size_t)vh * SEQ + t0 + t) * D + dc * 8);
        }
    };

    // ---- prologue: Q (swizzled) + K0 in group0; V0 in group1 ----
    #pragma unroll
    for (int i = 0; i < 8; ++i) {
        const int f = tid + i * THREADS;              // 0..2047
        const int qh = f >> 8, rem = f & 255;
        const int s = rem >> 3, kc = rem & 7;
        cp16(sb + SM_Q + qh * QS_H + s * 128 + ((kc ^ (s & 7)) << 4),
             g_Q16 + kv16 + ((size_t)qh * SEQ + s0 + s) * D + kc * 8);
    }
    prefetch_K(0);
    cp_commit();                 // group: Q + K0
    prefetch_V(0);
    cp_commit();                 // group: V0
    cp_wait0();
    __syncthreads();

    float o[2][8][4];
    #pragma unroll
    for (int mt = 0; mt < 2; ++mt)
        #pragma unroll
        for (int n = 0; n < 8; ++n)
            #pragma unroll
            for (int i = 0; i < 4; ++i) o[mt][n][i] = 0.f;

    // per-warp bases (swizzle xors are lane-derived constants)
    const uint32_t qb0 = sb + SM_Q + h * QS_H + (lane & 15) * 128;
    const int      qx  = lane & 7;
    const uint32_t kb0 = sb + SM_K + h * KS_H + (lane & 15) * 64;
    const int      kx  = lane & 3;
    const uint32_t vb0 = sb + SM_V + h * VS_H + (lane & 15) * 128;
    const int      vx  = lane & 7;
    const uint32_t wb0 = sb + SM_EW + h * EW_H + (lane & 15) * 64;
    const int      wx  = lane & 3;                 // (row&3) for W-ldsm rows
    const int      exx = (lane >> 2) & 3;          // (row&3) for E-store rows

    for (int t0g = 0; t0g < SEQ; t0g += T_TILE) {
        // ---- GEMM1: E[32s x 32t] = Qh @ K ; B-frags shared across 2 m-tiles ----
        float c1[2][4][4];
        #pragma unroll
        for (int mt = 0; mt < 2; ++mt)
            #pragma unroll
            for (int n = 0; n < 4; ++n)
                #pragma unroll
                for (int i = 0; i < 4; ++i) c1[mt][n][i] = 0.f;
        #pragma unroll
        for (int k0 = 0; k0 < 4; ++k0) {
            uint32_t a0[4], a1[4];
            const uint32_t qc = (uint32_t)(((((lane >> 4) + 2 * k0)) ^ qx) << 4);
            ldsm_x4(a0, qb0 + qc);
            ldsm_x4(a1, qb0 + 16 * 128 + qc);
            #pragma unroll
            for (int n0 = 0; n0 < 4; ++n0) {
                uint32_t bf[2];
                ldsm_x2t(bf, kb0 + k0 * 16 * 64 + ((n0 ^ kx) << 4));
                mma16816(c1[0][n0], a0, bf);
                mma16816(c1[1][n0], a1, bf);
            }
        }
        // ---- E -> f16 exchange (64B-row swizzled EW region) ----
        {
            char* ebase = smem + SM_EW + h * EW_H;
            const int cb = (lane & 3) * 4;
            #pragma unroll
            for (int mt = 0; mt < 2; ++mt) {
                const int r0 = mt * 16 + (lane >> 2);
                #pragma unroll
                for (int n0 = 0; n0 < 4; ++n0) {
                    const int sw = ((n0 ^ exx) << 4) + cb;
                    *(uint32_t*)(ebase + r0 * 64 + sw)       = packh2(c1[mt][n0][0], c1[mt][n0][1]);
                    *(uint32_t*)(ebase + (r0 + 8) * 64 + sw) = packh2(c1[mt][n0][2], c1[mt][n0][3]);
                }
            }
        }
        __syncthreads();                       // #1: E visible, K reads done
        if (t0g + T_TILE < SEQ) prefetch_K(t0g + T_TILE);
        cp_commit();                           // group K(i+1)

        // ---- softmax over 8 heads, in place, 8B vectors ----
        {
            const int s = tid >> 3, tq = tid & 7;
            const int off = s * 64 + ((((tq >> 1) ^ (s & 3))) << 4) + (tq & 1) * 8;
            float ex[8][4];
            float sum0 = 0.f, sum1 = 0.f, sum2 = 0.f, sum3 = 0.f;
            #pragma unroll
            for (int hh = 0; hh < 8; ++hh) {
                uint2 v = *(const uint2*)(smem + SM_EW + hh * EW_H + off);
                float2 fa = __half22float2(*(const __half2*)&v.x);
                float2 fb = __half22float2(*(const __half2*)&v.y);
                ex[hh][0] = __expf(fa.x); ex[hh][1] = __expf(fa.y);
                ex[hh][2] = __expf(fb.x); ex[hh][3] = __expf(fb.y);
                sum0 += ex[hh][0]; sum1 += ex[hh][1];
                sum2 += ex[hh][2]; sum3 += ex[hh][3];
            }
            const float r0 = __fdividef(1.f, sum0);
            const float r1 = __fdividef(1.f, sum1);
            const float r2 = __fdividef(1.f, sum2);
            const float r3 = __fdividef(1.f, sum3);
            #pragma unroll
            for (int hh = 0; hh < 8; ++hh) {
                uint2 w;
                w.x = packh2(ex[hh][0] * r0, ex[hh][1] * r1);
                w.y = packh2(ex[hh][2] * r2, ex[hh][3] * r3);
                *(uint2*)(smem + SM_EW + hh * EW_H + off) = w;
            }
        }
        cp_wait1();                            // V(i) resident (K(i+1) may fly)
        __syncthreads();                       // #2: W + V(i) visible CTA-wide

        // ---- GEMM2: O += W[32s x 32t] @ V[32t x 64dv] ; B-frags shared ----
        {
            uint32_t a2[2][2][4];
            #pragma unroll
            for (int mt = 0; mt < 2; ++mt)
                #pragma unroll
                for (int k0 = 0; k0 < 2; ++k0)
                    ldsm_x4(a2[mt][k0],
                            wb0 + mt * 16 * 64 + (((2 * k0 + (lane >> 4)) ^ wx) << 4));
            #pragma unroll
            for (int n0 = 0; n0 < 8; ++n0) {
                #pragma unroll
                for (int k0 = 0; k0 < 2; ++k0) {
                    uint32_t bf[2];
                    ldsm_x2t(bf, vb0 + k0 * 16 * 128 + ((n0 ^ vx) << 4));
                    mma16816(o[0][n0], a2[0][k0], bf);
                    mma16816(o[1][n0], a2[1][k0], bf);
                }
            }
        }
        __syncthreads();                       // #3: V reads done, W consumed
        if (t0g + T_TILE < SEQ) prefetch_V(t0g + T_TILE);
        cp_commit();                           // group V(i+1)
        cp_wait1();                            // K(i+1) resident (V(i+1) may fly)
        __syncthreads();                       // #4: K(i+1) visible CTA-wide
    }

    // ---- writeback: raw [B,H,S,64] order ----
    {
        const int c = (lane & 3) * 2;
        #pragma unroll
        for (int mt = 0; mt < 2; ++mt) {
            const int r = mt * 16 + (lane >> 2);
            float* dst = O + (((size_t)(b * NH + h)) * SEQ + (s0 + r)) * D;
            #pragma unroll
            for (int n0 = 0; n0 < 8; ++n0) {
                *(float2*)(dst + n0 * 8 + c)         = make_float2(o[mt][n0][0], o[mt][n0][1]);
                *(float2*)(dst + 8 * D + n0 * 8 + c) = make_float2(o[mt][n0][2], o[mt][n0][3]);
            }
        }
    }
}

extern "C" void kernel_launch(void* const* d_in, const int* in_sizes, int n_in,
                              void* d_out, int out_size) {
    (void)in_sizes; (void)n_in; (void)out_size;
    const float* Q = (const float*)d_in[0];
    const float* K = (const float*)d_in[1];
    const float* V = (const float*)d_in[2];
    float* O = (float*)d_out;
    cvt_qkv_kernel<<<KV_ELEMS / 8 / 256, 256>>>(Q, K, V);
    cudaFuncSetAttribute(attn_hmma_kernel,
                         cudaFuncAttributeMaxDynamicSharedMemorySize, SMEM_BYTES);
    attn_hmma_kernel<<<2 * (SEQ / S_TILE), THREADS, SMEM_BYTES>>>(O);
}

// round 16
// speedup vs baseline: 1.0427x; 1.0427x over previous
#include <cuda_runtime.h>
#include <cuda_fp16.h>
#include <cstdint>

// Head-axis-softmax attention, HMMA fp16/f32. R16:
//  - R14 base (S_TILE=64, grid 128 = one wave, 512 thr, warp=(head, s-half))
//  - cross-tile fusion: [GEMM2(i) || GEMM1(i+1)] in one phase, 2 barriers/tile
//  - EW ping-pong buffers, 64B swizzled rows (R15-verified addressing)
//  - K single-buffered, V double-buffered; one commit+wait_group0 per epoch
//  - pre-pass converts Q (scale folded), K, V to f16

namespace {
constexpr int NH = 8, SEQ = 4096, D = 64;
constexpr int S_TILE = 64, T_TILE = 32;
constexpr int THREADS = 512;
constexpr float SCALE = 0.044194173824159216f;   // 1/sqrt(512)

constexpr int KS_H = 64 * 64;        // K: per head 64 k-rows x 64B (32 t f16), SW64
constexpr int VS_H = 32 * 128;       // V: per head 32 t-rows x 128B (64 dv f16), SW128
constexpr int QS_H = 64 * 128;       // Q: per head 64 s-rows x 128B (64 k f16), SW128
constexpr int EW_H = 64 * 64;        // E/W: per head 64 s-rows x 64B (32 t f16), swizzled

constexpr int VS_BUF = NH * VS_H;                 // 32768
constexpr int EW_BUF = NH * EW_H;                 // 32768
constexpr int SM_K  = 0;                          // 32768
constexpr int SM_V  = NH * KS_H;                  // 32768 .. +65536 (2 bufs)
constexpr int SM_Q  = SM_V + 2 * VS_BUF;          // 98304 .. +65536
constexpr int SM_EW = SM_Q + NH * QS_H;           // 163840 .. +65536 (2 bufs)
constexpr int SMEM_BYTES = SM_EW + 2 * EW_BUF;    // 229376 <= 232448

constexpr int KV_ELEMS = 2 * NH * D * SEQ;
}

static __device__ __align__(16) __half g_Q16[KV_ELEMS];   // pre-scaled
static __device__ __align__(16) __half g_K16[KV_ELEMS];
static __device__ __align__(16) __half g_V16[KV_ELEMS];

__global__ __launch_bounds__(256) void cvt_qkv_kernel(const float* __restrict__ Q,
                                                      const float* __restrict__ K,
                                                      const float* __restrict__ V) {
    const int i = (blockIdx.x * 256 + threadIdx.x) * 8;
    {
        float4 a = *(const float4*)(Q + i);
        float4 b = *(const float4*)(Q + i + 4);
        __half2 p[4] = { __floats2half2_rn(a.x * SCALE, a.y * SCALE),
                         __floats2half2_rn(a.z * SCALE, a.w * SCALE),
                         __floats2half2_rn(b.x * SCALE, b.y * SCALE),
                         __floats2half2_rn(b.z * SCALE, b.w * SCALE) };
        *(uint4*)&g_Q16[i] = *(const uint4*)p;
    }
    {
        float4 a = *(const float4*)(K + i);
        float4 b = *(const float4*)(K + i + 4);
        __half2 p[4] = { __floats2half2_rn(a.x, a.y), __floats2half2_rn(a.z, a.w),
                         __floats2half2_rn(b.x, b.y), __floats2half2_rn(b.z, b.w) };
        *(uint4*)&g_K16[i] = *(const uint4*)p;
    }
    {
        float4 a = *(const float4*)(V + i);
        float4 b = *(const float4*)(V + i + 4);
        __half2 p[4] = { __floats2half2_rn(a.x, a.y), __floats2half2_rn(a.z, a.w),
                         __floats2half2_rn(b.x, b.y), __floats2half2_rn(b.z, b.w) };
        *(uint4*)&g_V16[i] = *(const uint4*)p;
    }
}

static __device__ __forceinline__ uint32_t smem_u32(const void* p) {
    uint32_t a;
    asm("{ .reg .u64 t; cvta.to.shared.u64 t, %1; cvt.u32.u64 %0, t; }" : "=r"(a) : "l"(p));
    return a;
}
static __device__ __forceinline__ void cp16(uint32_t dst, const void* src) {
    asm volatile("cp.async.cg.shared.global [%0], [%1], 16;" :: "r"(dst), "l"(src));
}
static __device__ __forceinline__ void cp_commit() {
    asm volatile("cp.async.commit_group;" ::: "memory");
}
static __device__ __forceinline__ void cp_wait0() {
    asm volatile("cp.async.wait_group 0;" ::: "memory");
}
static __device__ __forceinline__ void ldsm_x4(uint32_t* r, uint32_t a) {
    asm volatile("ldmatrix.sync.aligned.m8n8.x4.shared.b16 {%0,%1,%2,%3}, [%4];"
        : "=r"(r[0]), "=r"(r[1]), "=r"(r[2]), "=r"(r[3]) : "r"(a));
}
static __device__ __forceinline__ void ldsm_x2t(uint32_t* r, uint32_t a) {
    asm volatile("ldmatrix.sync.aligned.m8n8.x2.trans.shared.b16 {%0,%1}, [%2];"
        : "=r"(r[0]), "=r"(r[1]) : "r"(a));
}
static __device__ __forceinline__ void mma16816(float* c, const uint32_t* a, const uint32_t* b) {
    asm volatile("mma.sync.aligned.m16n8k16.row.col.f32.f16.f16.f32 "
        "{%0,%1,%2,%3}, {%4,%5,%6,%7}, {%8,%9}, {%0,%1,%2,%3};"
        : "+f"(c[0]), "+f"(c[1]), "+f"(c[2]), "+f"(c[3])
        : "r"(a[0]), "r"(a[1]), "r"(a[2]), "r"(a[3]), "r"(b[0]), "r"(b[1]));
}
static __device__ __forceinline__ uint32_t packh2(float x, float y) {
    __half2 h = __floats2half2_rn(x, y);
    return *(const uint32_t*)&h;
}

__global__ __launch_bounds__(THREADS, 1)
void attn_hmma_kernel(float* __restrict__ O)
{
    extern __shared__ char smem[];
    const uint32_t sb = smem_u32(smem);
    const int tid  = threadIdx.x;
    const int wid  = tid >> 5, lane = tid & 31;
    const int b    = blockIdx.x >> 6;
    const int s0   = (blockIdx.x & 63) * S_TILE;
    const int h    = wid >> 1;
    const int half = wid & 1;

    const size_t kv16 = (size_t)b * NH * D * SEQ;

    auto prefetch_K = [&](int t0) {
        #pragma unroll
        for (int i = 0; i < 4; ++i) {
            const int f = tid + i * THREADS;          // 0..2047 16B chunks
            const int kh = f >> 8, rem = f & 255;
            const int k = rem >> 2, tc = rem & 3;
            cp16(sb + SM_K + kh * KS_H + k * 64 + ((tc ^ (k & 3)) << 4),
                 g_K16 + kv16 + (size_t)(kh * D + k) * SEQ + t0 + tc * 8);
        }
    };
    auto prefetch_V = [&](int t0, int buf) {
        const uint32_t vdst = sb + SM_V + buf * VS_BUF;
        #pragma unroll
        for (int i = 0; i < 4; ++i) {
            const int f = tid + i * THREADS;
            const int vh = f >> 8, rem = f & 255;
            const int t = rem >> 3, dc = rem & 7;
            cp16(vdst + vh * VS_H + t * 128 + ((dc ^ (t & 7)) << 4),
                 g_V16 + kv16 + ((size_t)vh * SEQ + t0 + t) * D + dc * 8);
        }
    };

    // ---- prologue: Q (swizzled) + K0 + V0 ----
    #pragma unroll
    for (int i = 0; i < 8; ++i) {
        const int f = tid + i * THREADS;              // 0..4095 16B chunks
        const int qh = f >> 9, rem = f & 511;
        const int s = rem >> 3, kc = rem & 7;
        cp16(sb + SM_Q + qh * QS_H + s * 128 + ((kc ^ (s & 7)) << 4),
             g_Q16 + kv16 + ((size_t)qh * SEQ + s0 + s) * D + kc * 8);
    }
    prefetch_K(0);
    prefetch_V(0, 0);
    cp_commit();
    cp_wait0();
    __syncthreads();

    float o[2][8][4];
    #pragma unroll
    for (int mt = 0; mt < 2; ++mt)
        #pragma unroll
        for (int n = 0; n < 8; ++n)
            #pragma unroll
            for (int i = 0; i < 4; ++i) o[mt][n][i] = 0.f;

    // per-warp bases (swizzle xors are lane-derived constants)
    const uint32_t qb0 = sb + SM_Q + h * QS_H + (half * 32 + (lane & 15)) * 128;
    const int      qx  = lane & 7;
    const uint32_t kb0 = sb + SM_K + h * KS_H + (lane & 15) * 64;
    const int      kx  = lane & 3;
    const uint32_t vb0r = h * VS_H + (lane & 15) * 128;
    const int      vx  = lane & 7;
    const uint32_t wrow = (half * 32 + (lane & 15)) * 64;   // W-ldsm row offset
    const int      wx  = lane & 3;
    const int      exx = (lane >> 2) & 3;                   // E-store (row&3)

    // ---- GEMM1 + E-store into EW[buf] (lambda) ----
    auto gemm1_estore = [&](int ewbuf) {
        float c1[2][4][4];
        #pragma unroll
        for (int mt = 0; mt < 2; ++mt)
            #pragma unroll
            for (int n = 0; n < 4; ++n)
                #pragma unroll
                for (int i = 0; i < 4; ++i) c1[mt][n][i] = 0.f;
        #pragma unroll
        for (int k0 = 0; k0 < 4; ++k0) {
            uint32_t a0[4], a1[4];
            const uint32_t qc = (uint32_t)((((lane >> 4) + 2 * k0) ^ qx) << 4);
            ldsm_x4(a0, qb0 + qc);
            ldsm_x4(a1, qb0 + 16 * 128 + qc);
            #pragma unroll
            for (int n0 = 0; n0 < 4; ++n0) {
                uint32_t bf[2];
                ldsm_x2t(bf, kb0 + k0 * 16 * 64 + ((n0 ^ kx) << 4));
                mma16816(c1[0][n0], a0, bf);
                mma16816(c1[1][n0], a1, bf);
            }
        }
        char* ebase = smem + SM_EW + ewbuf * EW_BUF + h * EW_H;
        const int cb = (lane & 3) * 4;
        #pragma unroll
        for (int mt = 0; mt < 2; ++mt) {
            const int r0 = half * 32 + mt * 16 + (lane >> 2);
            #pragma unroll
            for (int n0 = 0; n0 < 4; ++n0) {
                const int sw = ((n0 ^ exx) << 4) + cb;
                *(uint32_t*)(ebase + r0 * 64 + sw)       = packh2(c1[mt][n0][0], c1[mt][n0][1]);
                *(uint32_t*)(ebase + (r0 + 8) * 64 + sw) = packh2(c1[mt][n0][2], c1[mt][n0][3]);
            }
        }
    };

    // ---- prologue compute: E(0) -> EW[0]; then prefetch K1,V1 ----
    gemm1_estore(0);
    __syncthreads();
    prefetch_K(T_TILE);
    prefetch_V(T_TILE, 1);
    cp_commit();

    for (int i = 0; i < 128; ++i) {
        const int buf = i & 1;

        // ---- softmax over 8 heads on EW[buf], in place, 8B vectors ----
        {
            const int s = tid >> 3, tq = tid & 7;
            const int off = s * 64 + (((tq >> 1) ^ (s & 3)) << 4) + (tq & 1) * 8;
            char* ew = smem + SM_EW + buf * EW_BUF;
            float ex[8][4];
            float sum0 = 0.f, sum1 = 0.f, sum2 = 0.f, sum3 = 0.f;
            #pragma unroll
            for (int hh = 0; hh < 8; ++hh) {
                uint2 v = *(const uint2*)(ew + hh * EW_H + off);
                float2 fa = __half22float2(*(const __half2*)&v.x);
                float2 fb = __half22float2(*(const __half2*)&v.y);
                ex[hh][0] = __expf(fa.x); ex[hh][1] = __expf(fa.y);
                ex[hh][2] = __expf(fb.x); ex[hh][3] = __expf(fb.y);
                sum0 += ex[hh][0]; sum1 += ex[hh][1];
                sum2 += ex[hh][2]; sum3 += ex[hh][3];
            }
            const float r0 = __fdividef(1.f, sum0);
            const float r1 = __fdividef(1.f, sum1);
            const float r2 = __fdividef(1.f, sum2);
            const float r3 = __fdividef(1.f, sum3);
            #pragma unroll
            for (int hh = 0; hh < 8; ++hh) {
                uint2 w;
                w.x = packh2(ex[hh][0] * r0, ex[hh][1] * r1);
                w.y = packh2(ex[hh][2] * r2, ex[hh][3] * r3);
                *(uint2*)(ew + hh * EW_H + off) = w;
            }
        }
        cp_wait0();                       // K(i+1), V(i+1) resident
        __syncthreads();                  // bar A: W(i) + staged tiles visible

        // ---- fused phase: GEMM2(i) || GEMM1(i+1) + E-store(i+1) ----
        {
            const uint32_t wb = sb + SM_EW + buf * EW_BUF + h * EW_H + wrow;
            const uint32_t vb = sb + SM_V + buf * VS_BUF + vb0r;
            uint32_t a2[2][2][4];
            #pragma unroll
            for (int mt = 0; mt < 2; ++mt)
                #pragma unroll
                for (int k0 = 0; k0 < 2; ++k0)
                    ldsm_x4(a2[mt][k0],
                            wb + mt * 16 * 64 + (((2 * k0 + (lane >> 4)) ^ wx) << 4));
            #pragma unroll
            for (int n0 = 0; n0 < 8; ++n0) {
                #pragma unroll
                for (int k0 = 0; k0 < 2; ++k0) {
                    uint32_t bf[2];
                    ldsm_x2t(bf, vb + k0 * 16 * 128 + ((n0 ^ vx) << 4));
                    mma16816(o[0][n0], a2[0][k0], bf);
                    mma16816(o[1][n0], a2[1][k0], bf);
                }
            }
        }
        if (i < 127) gemm1_estore(buf ^ 1);
        __syncthreads();                  // bar B: E(i+1) visible; K/V reads done

        if (i < 126) {
            prefetch_K((i + 2) * T_TILE);
            prefetch_V((i + 2) * T_TILE, buf);
        }
        cp_commit();
    }

    // ---- writeback: raw [B,H,S,64] order ----
    {
        const int c = (lane & 3) * 2;
        #pragma unroll
        for (int mt = 0; mt < 2; ++mt) {
            const int r = half * 32 + mt * 16 + (lane >> 2);
            float* dst = O + (((size_t)(b * NH + h)) * SEQ + (s0 + r)) * D;
            #pragma unroll
            for (int n0 = 0; n0 < 8; ++n0) {
                *(float2*)(dst + n0 * 8 + c)         = make_float2(o[mt][n0][0], o[mt][n0][1]);
                *(float2*)(dst + 8 * D + n0 * 8 + c) = make_float2(o[mt][n0][2], o[mt][n0][3]);
            }
        }
    }
}

extern "C" void kernel_launch(void* const* d_in, const int* in_sizes, int n_in,
                              void* d_out, int out_size) {
    (void)in_sizes; (void)n_in; (void)out_size;
    const float* Q = (const float*)d_in[0];
    const float* K = (const float*)d_in[1];
    const float* V = (const float*)d_in[2];
    float* O = (float*)d_out;
    cvt_qkv_kernel<<<KV_ELEMS / 8 / 256, 256>>>(Q, K, V);
    cudaFuncSetAttribute(attn_hmma_kernel,
                         cudaFuncAttributeMaxDynamicSharedMemorySize, SMEM_BYTES);
    attn_hmma_kernel<<<2 * (SEQ / S_TILE), THREADS, SMEM_BYTES>>>(O);
}

// round 17
// speedup vs baseline: 1.0825x; 1.0381x over previous
#include <cuda_runtime.h>
#include <cuda_fp16.h>
#include <cstdint>

// Head-axis-softmax attention, HMMA fp16/f32. R17 = R16 + persistent Q frags:
//  - Q A-fragments loaded ONCE into registers (qa, 32 regs); Q smem read once
//  - GEMM1 split into two n-halves (c1 16 regs) to fit the 128-reg budget
//  - otherwise identical to R16: S_TILE=64, grid 128 (one wave), 512 thr,
//    fused [GEMM2(i) || GEMM1(i+1)], EW ping-pong, K single / V double buffer

namespace {
constexpr int NH = 8, SEQ = 4096, D = 64;
constexpr int S_TILE = 64, T_TILE = 32;
constexpr int THREADS = 512;
constexpr float SCALE = 0.044194173824159216f;   // 1/sqrt(512)

constexpr int KS_H = 64 * 64;        // K: per head 64 k-rows x 64B (32 t f16), SW64
constexpr int VS_H = 32 * 128;       // V: per head 32 t-rows x 128B (64 dv f16), SW128
constexpr int QS_H = 64 * 128;       // Q: per head 64 s-rows x 128B (64 k f16), SW128
constexpr int EW_H = 64 * 64;        // E/W: per head 64 s-rows x 64B (32 t f16), swizzled

constexpr int VS_BUF = NH * VS_H;                 // 32768
constexpr int EW_BUF = NH * EW_H;                 // 32768
constexpr int SM_K  = 0;                          // 32768
constexpr int SM_V  = NH * KS_H;                  // 32768 .. +65536 (2 bufs)
constexpr int SM_Q  = SM_V + 2 * VS_BUF;          // 98304 .. +65536
constexpr int SM_EW = SM_Q + NH * QS_H;           // 163840 .. +65536 (2 bufs)
constexpr int SMEM_BYTES = SM_EW + 2 * EW_BUF;    // 229376 <= 232448

constexpr int KV_ELEMS = 2 * NH * D * SEQ;
}

static __device__ __align__(16) __half g_Q16[KV_ELEMS];   // pre-scaled
static __device__ __align__(16) __half g_K16[KV_ELEMS];
static __device__ __align__(16) __half g_V16[KV_ELEMS];

__global__ __launch_bounds__(256) void cvt_qkv_kernel(const float* __restrict__ Q,
                                                      const float* __restrict__ K,
                                                      const float* __restrict__ V) {
    const int i = (blockIdx.x * 256 + threadIdx.x) * 8;
    {
        float4 a = *(const float4*)(Q + i);
        float4 b = *(const float4*)(Q + i + 4);
        __half2 p[4] = { __floats2half2_rn(a.x * SCALE, a.y * SCALE),
                         __floats2half2_rn(a.z * SCALE, a.w * SCALE),
                         __floats2half2_rn(b.x * SCALE, b.y * SCALE),
                         __floats2half2_rn(b.z * SCALE, b.w * SCALE) };
        *(uint4*)&g_Q16[i] = *(const uint4*)p;
    }
    {
        float4 a = *(const float4*)(K + i);
        float4 b = *(const float4*)(K + i + 4);
        __half2 p[4] = { __floats2half2_rn(a.x, a.y), __floats2half2_rn(a.z, a.w),
                         __floats2half2_rn(b.x, b.y), __floats2half2_rn(b.z, b.w) };
        *(uint4*)&g_K16[i] = *(const uint4*)p;
    }
    {
        float4 a = *(const float4*)(V + i);
        float4 b = *(const float4*)(V + i + 4);
        __half2 p[4] = { __floats2half2_rn(a.x, a.y), __floats2half2_rn(a.z, a.w),
                         __floats2half2_rn(b.x, b.y), __floats2half2_rn(b.z, b.w) };
        *(uint4*)&g_V16[i] = *(const uint4*)p;
    }
}

static __device__ __forceinline__ uint32_t smem_u32(const void* p) {
    uint32_t a;
    asm("{ .reg .u64 t; cvta.to.shared.u64 t, %1; cvt.u32.u64 %0, t; }" : "=r"(a) : "l"(p));
    return a;
}
static __device__ __forceinline__ void cp16(uint32_t dst, const void* src) {
    asm volatile("cp.async.cg.shared.global [%0], [%1], 16;" :: "r"(dst), "l"(src));
}
static __device__ __forceinline__ void cp_commit() {
    asm volatile("cp.async.commit_group;" ::: "memory");
}
static __device__ __forceinline__ void cp_wait0() {
    asm volatile("cp.async.wait_group 0;" ::: "memory");
}
static __device__ __forceinline__ void ldsm_x4(uint32_t* r, uint32_t a) {
    asm volatile("ldmatrix.sync.aligned.m8n8.x4.shared.b16 {%0,%1,%2,%3}, [%4];"
        : "=r"(r[0]), "=r"(r[1]), "=r"(r[2]), "=r"(r[3]) : "r"(a));
}
static __device__ __forceinline__ void ldsm_x2t(uint32_t* r, uint32_t a) {
    asm volatile("ldmatrix.sync.aligned.m8n8.x2.trans.shared.b16 {%0,%1}, [%2];"
        : "=r"(r[0]), "=r"(r[1]) : "r"(a));
}
static __device__ __forceinline__ void mma16816(float* c, const uint32_t* a, const uint32_t* b) {
    asm volatile("mma.sync.aligned.m16n8k16.row.col.f32.f16.f16.f32 "
        "{%0,%1,%2,%3}, {%4,%5,%6,%7}, {%8,%9}, {%0,%1,%2,%3};"
        : "+f"(c[0]), "+f"(c[1]), "+f"(c[2]), "+f"(c[3])
        : "r"(a[0]), "r"(a[1]), "r"(a[2]), "r"(a[3]), "r"(b[0]), "r"(b[1]));
}
static __device__ __forceinline__ uint32_t packh2(float x, float y) {
    __half2 h = __floats2half2_rn(x, y);
    return *(const uint32_t*)&h;
}

__global__ __launch_bounds__(THREADS, 1)
void attn_hmma_kernel(float* __restrict__ O)
{
    extern __shared__ char smem[];
    const uint32_t sb = smem_u32(smem);
    const int tid  = threadIdx.x;
    const int wid  = tid >> 5, lane = tid & 31;
    const int b    = blockIdx.x >> 6;
    const int s0   = (blockIdx.x & 63) * S_TILE;
    const int h    = wid >> 1;
    const int half = wid & 1;

    const size_t kv16 = (size_t)b * NH * D * SEQ;

    auto prefetch_K = [&](int t0) {
        #pragma unroll
        for (int i = 0; i < 4; ++i) {
            const int f = tid + i * THREADS;          // 0..2047 16B chunks
            const int kh = f >> 8, rem = f & 255;
            const int k = rem >> 2, tc = rem & 3;
            cp16(sb + SM_K + kh * KS_H + k * 64 + ((tc ^ (k & 3)) << 4),
                 g_K16 + kv16 + (size_t)(kh * D + k) * SEQ + t0 + tc * 8);
        }
    };
    auto prefetch_V = [&](int t0, int buf) {
        const uint32_t vdst = sb + SM_V + buf * VS_BUF;
        #pragma unroll
        for (int i = 0; i < 4; ++i) {
            const int f = tid + i * THREADS;
            const int vh = f >> 8, rem = f & 255;
            const int t = rem >> 3, dc = rem & 7;
            cp16(vdst + vh * VS_H + t * 128 + ((dc ^ (t & 7)) << 4),
                 g_V16 + kv16 + ((size_t)vh * SEQ + t0 + t) * D + dc * 8);
        }
    };

    // ---- prologue: Q (swizzled) + K0 + V0 ----
    #pragma unroll
    for (int i = 0; i < 8; ++i) {
        const int f = tid + i * THREADS;              // 0..4095 16B chunks
        const int qh = f >> 9, rem = f & 511;
        const int s = rem >> 3, kc = rem & 7;
        cp16(sb + SM_Q + qh * QS_H + s * 128 + ((kc ^ (s & 7)) << 4),
             g_Q16 + kv16 + ((size_t)qh * SEQ + s0 + s) * D + kc * 8);
    }
    prefetch_K(0);
    prefetch_V(0, 0);
    cp_commit();
    cp_wait0();
    __syncthreads();

    // ---- persistent Q A-fragments: qa[mt][k0][4] (32 regs), loaded ONCE ----
    uint32_t qa[2][4][4];
    {
        const uint32_t qb0 = sb + SM_Q + h * QS_H + (half * 32 + (lane & 15)) * 128;
        const int      qx  = lane & 7;
        #pragma unroll
        for (int k0 = 0; k0 < 4; ++k0) {
            const uint32_t qc = (uint32_t)((((lane >> 4) + 2 * k0) ^ qx) << 4);
            ldsm_x4(qa[0][k0], qb0 + qc);
            ldsm_x4(qa[1][k0], qb0 + 16 * 128 + qc);
        }
    }

    float o[2][8][4];
    #pragma unroll
    for (int mt = 0; mt < 2; ++mt)
        #pragma unroll
        for (int n = 0; n < 8; ++n)
            #pragma unroll
            for (int i = 0; i < 4; ++i) o[mt][n][i] = 0.f;

    // per-warp bases (swizzle xors are lane-derived constants)
    const uint32_t kb0 = sb + SM_K + h * KS_H + (lane & 15) * 64;
    const int      kx  = lane & 3;
    const uint32_t vb0r = h * VS_H + (lane & 15) * 128;
    const int      vx  = lane & 7;
    const uint32_t wrow = (half * 32 + (lane & 15)) * 64;   // W-ldsm row offset
    const int      wx  = lane & 3;
    const int      exx = (lane >> 2) & 3;                   // E-store (row&3)

    // ---- GEMM1 + E-store into EW[buf]; two n-halves (c1 = 16 regs each) ----
    auto gemm1_estore = [&](int ewbuf) {
        char* ebase = smem + SM_EW + ewbuf * EW_BUF + h * EW_H;
        const int cb = (lane & 3) * 4;
        #pragma unroll
        for (int nh = 0; nh < 2; ++nh) {
            float c1[2][2][4];
            #pragma unroll
            for (int mt = 0; mt < 2; ++mt)
                #pragma unroll
                for (int n = 0; n < 2; ++n)
                    #pragma unroll
                    for (int i = 0; i < 4; ++i) c1[mt][n][i] = 0.f;
            #pragma unroll
            for (int k0 = 0; k0 < 4; ++k0) {
                #pragma unroll
                for (int n0 = 0; n0 < 2; ++n0) {
                    const int n = nh * 2 + n0;
                    uint32_t bf[2];
                    ldsm_x2t(bf, kb0 + k0 * 16 * 64 + ((n ^ kx) << 4));
                    mma16816(c1[0][n0], qa[0][k0], bf);
                    mma16816(c1[1][n0], qa[1][k0], bf);
                }
            }
            #pragma unroll
            for (int mt = 0; mt < 2; ++mt) {
                const int r0 = half * 32 + mt * 16 + (lane >> 2);
                #pragma unroll
                for (int n0 = 0; n0 < 2; ++n0) {
                    const int n = nh * 2 + n0;
                    const int sw = ((n ^ exx) << 4) + cb;
                    *(uint32_t*)(ebase + r0 * 64 + sw) =
                        packh2(c1[mt][n0][0], c1[mt][n0][1]);
                    *(uint32_t*)(ebase + (r0 + 8) * 64 + sw) =
                        packh2(c1[mt][n0][2], c1[mt][n0][3]);
                }
            }
        }
    };

    // ---- prologue compute: E(0) -> EW[0]; then prefetch K1,V1 ----
    gemm1_estore(0);
    __syncthreads();
    prefetch_K(T_TILE);
    prefetch_V(T_TILE, 1);
    cp_commit();

    for (int i = 0; i < 128; ++i) {
        const int buf = i & 1;

        // ---- softmax over 8 heads on EW[buf], in place, 8B vectors ----
        {
            const int s = tid >> 3, tq = tid & 7;
            const int off = s * 64 + (((tq >> 1) ^ (s & 3)) << 4) + (tq & 1) * 8;
            char* ew = smem + SM_EW + buf * EW_BUF;
            float ex[8][4];
            float sum0 = 0.f, sum1 = 0.f, sum2 = 0.f, sum3 = 0.f;
            #pragma unroll
            for (int hh = 0; hh < 8; ++hh) {
                uint2 v = *(const uint2*)(ew + hh * EW_H + off);
                float2 fa = __half22float2(*(const __half2*)&v.x);
                float2 fb = __half22float2(*(const __half2*)&v.y);
                ex[hh][0] = __expf(fa.x); ex[hh][1] = __expf(fa.y);
                ex[hh][2] = __expf(fb.x); ex[hh][3] = __expf(fb.y);
                sum0 += ex[hh][0]; sum1 += ex[hh][1];
                sum2 += ex[hh][2]; sum3 += ex[hh][3];
            }
            const float r0 = __fdividef(1.f, sum0);
            const float r1 = __fdividef(1.f, sum1);
            const float r2 = __fdividef(1.f, sum2);
            const float r3 = __fdividef(1.f, sum3);
            #pragma unroll
            for (int hh = 0; hh < 8; ++hh) {
                uint2 w;
                w.x = packh2(ex[hh][0] * r0, ex[hh][1] * r1);
                w.y = packh2(ex[hh][2] * r2, ex[hh][3] * r3);
                *(uint2*)(ew + hh * EW_H + off) = w;
            }
        }
        cp_wait0();                       // K(i+1), V(i+1) resident
        __syncthreads();                  // bar A: W(i) + staged tiles visible

        // ---- fused phase: GEMM2(i) || GEMM1(i+1) + E-store(i+1) ----
        {
            const uint32_t wb = sb + SM_EW + buf * EW_BUF + h * EW_H + wrow;
            const uint32_t vb = sb + SM_V + buf * VS_BUF + vb0r;
            uint32_t a2[2][2][4];
            #pragma unroll
            for (int mt = 0; mt < 2; ++mt)
                #pragma unroll
                for (int k0 = 0; k0 < 2; ++k0)
                    ldsm_x4(a2[mt][k0],
                            wb + mt * 16 * 64 + (((2 * k0 + (lane >> 4)) ^ wx) << 4));
            #pragma unroll
            for (int n0 = 0; n0 < 8; ++n0) {
                #pragma unroll
                for (int k0 = 0; k0 < 2; ++k0) {
                    uint32_t bf[2];
                    ldsm_x2t(bf, vb + k0 * 16 * 128 + ((n0 ^ vx) << 4));
                    mma16816(o[0][n0], a2[0][k0], bf);
                    mma16816(o[1][n0], a2[1][k0], bf);
                }
            }
        }
        if (i < 127) gemm1_estore(buf ^ 1);
        __syncthreads();                  // bar B: E(i+1) visible; K/V reads done

        if (i < 126) {
            prefetch_K((i + 2) * T_TILE);
            prefetch_V((i + 2) * T_TILE, buf);
        }
        cp_commit();
    }

    // ---- writeback: raw [B,H,S,64] order ----
    {
        const int c = (lane & 3) * 2;
        #pragma unroll
        for (int mt = 0; mt < 2; ++mt) {
            const int r = half * 32 + mt * 16 + (lane >> 2);
            float* dst = O + (((size_t)(b * NH + h)) * SEQ + (s0 + r)) * D;
            #pragma unroll
            for (int n0 = 0; n0 < 8; ++n0) {
                *(float2*)(dst + n0 * 8 + c)         = make_float2(o[mt][n0][0], o[mt][n0][1]);
                *(float2*)(dst + 8 * D + n0 * 8 + c) = make_float2(o[mt][n0][2], o[mt][n0][3]);
            }
        }
    }
}

extern "C" void kernel_launch(void* const* d_in, const int* in_sizes, int n_in,
                              void* d_out, int out_size) {
    (void)in_sizes; (void)n_in; (void)out_size;
    const float* Q = (const float*)d_in[0];
    const float* K = (const float*)d_in[1];
    const float* V = (const float*)d_in[2];
    float* O = (float*)d_out;
    cvt_qkv_kernel<<<KV_ELEMS / 8 / 256, 256>>>(Q, K, V);
    cudaFuncSetAttribute(attn_hmma_kernel,
                         cudaFuncAttributeMaxDynamicSharedMemorySize, SMEM_BYTES);
    attn_hmma_kernel<<<2 * (SEQ / S_TILE), THREADS, SMEM_BYTES>>>(O);
}